// round 5
// baseline (speedup 1.0000x reference)
#include <cuda_runtime.h>
#include <cuda_fp16.h>
#include <cstdint>

#define K_DIM 1024
#define M_DIM 2048
#define N_DIM 1024
#define NCHUNK 64

// fp16 split planes, 64 B per row: A=[hi(32B)|lo(32B)], B=[whi(32B)|wlo(32B)]
__device__ __half g_A[(size_t)NCHUNK * M_DIM * 32];
__device__ __half g_B[(size_t)NCHUNK * N_DIM * 32];

// ---------------------------------------------------------------------------
// Fused prep: blocks [0,512) do X, [512,768) do W.
// ---------------------------------------------------------------------------
__global__ void prep_kernel(const float* __restrict__ X,
                            const float* __restrict__ W,
                            const float* __restrict__ vmap,
                            const float* __restrict__ wmap) {
    if (blockIdx.x < 512) {
        // ---- X: x_c/16 -> hi/lo. one thread per (r,m)
        int gid = blockIdx.x * 256 + threadIdx.x;
        int r = gid >> 11, m = gid & 2047;
        const float* src = X + (size_t)m * K_DIM + r * 16;
        float xs[16];
        ((float4*)xs)[0] = ((const float4*)src)[0];
        ((float4*)xs)[1] = ((const float4*)src)[1];
        ((float4*)xs)[2] = ((const float4*)src)[2];
        ((float4*)xs)[3] = ((const float4*)src)[3];
        unsigned hi[8], lo[8];
#pragma unroll
        for (int jj = 0; jj < 8; jj++) {
            unsigned short h[2], l[2];
#pragma unroll
            for (int e = 0; e < 2; e++) {
                int j = 2 * jj + e;
                float xv = xs[j];
                int idx = (int)(xv + 8.0f);
                idx = idx < 0 ? 0 : (idx > 15 ? 15 : idx);
                float xc = (xv + __ldg(vmap + j * 16 + idx)) * 0.0625f;
                __half hh = __float2half_rn(xc);
                __half ll = __float2half_rn(xc - __half2float(hh));
                h[e] = __half_as_ushort(hh);
                l[e] = __half_as_ushort(ll);
            }
            hi[jj] = h[0] | ((unsigned)h[1] << 16);
            lo[jj] = l[0] | ((unsigned)l[1] << 16);
        }
        uint4* dst = (uint4*)(g_A + ((size_t)r * M_DIM + m) * 32);
        dst[0] = make_uint4(hi[0], hi[1], hi[2], hi[3]);
        dst[1] = make_uint4(hi[4], hi[5], hi[6], hi[7]);
        dst[2] = make_uint4(lo[0], lo[1], lo[2], lo[3]);
        dst[3] = make_uint4(lo[4], lo[5], lo[6], lo[7]);
    } else {
        // ---- W: w_c -> hi/lo. idx over (r, n-block)
        int idx4 = blockIdx.x - 512;            // 0..255
        int r = idx4 >> 2;
        int n = (idx4 & 3) * 256 + threadIdx.x;
        unsigned hi[8], lo[8];
#pragma unroll
        for (int jj = 0; jj < 8; jj++) {
            unsigned short h[2], l[2];
#pragma unroll
            for (int e = 0; e < 2; e++) {
                int j = 2 * jj + e;
                float w = W[(size_t)(16 * r + j) * N_DIM + n];
                int idx = (int)(w + 8.0f);
                idx = idx < 0 ? 0 : (idx > 15 ? 15 : idx);
                float wc = w + __ldg(wmap + j * 16 + idx);
                __half hh = __float2half_rn(wc);
                __half ll = __float2half_rn(wc - __half2float(hh));
                h[e] = __half_as_ushort(hh);
                l[e] = __half_as_ushort(ll);
            }
            hi[jj] = h[0] | ((unsigned)h[1] << 16);
            lo[jj] = l[0] | ((unsigned)l[1] << 16);
        }
        uint4* dst = (uint4*)(g_B + ((size_t)r * N_DIM + n) * 32);
        dst[0] = make_uint4(hi[0], hi[1], hi[2], hi[3]);
        dst[1] = make_uint4(hi[4], hi[5], hi[6], hi[7]);
        dst[2] = make_uint4(lo[0], lo[1], lo[2], lo[3]);
        dst[3] = make_uint4(lo[4], lo[5], lo[6], lo[7]);
    }
}

// ---------------------------------------------------------------------------
#define LDSM4(R, addr)                                                         \
    asm volatile("ldmatrix.sync.aligned.m8n8.x4.shared.b16 {%0,%1,%2,%3}, [%4];" \
                 : "=r"((R)[0]), "=r"((R)[1]), "=r"((R)[2]), "=r"((R)[3])      \
                 : "r"(addr))

#define MMA16816(C, A0, A1, A2, A3, B0, B1)                                    \
    asm volatile("mma.sync.aligned.m16n8k16.row.col.f32.f16.f16.f32 "          \
                 "{%0,%1,%2,%3}, {%4,%5,%6,%7}, {%8,%9}, {%0,%1,%2,%3};"       \
                 : "+f"((C)[0]), "+f"((C)[1]), "+f"((C)[2]), "+f"((C)[3])      \
                 : "r"(A0), "r"(A1), "r"(A2), "r"(A3), "r"(B0), "r"(B1))

// swizzled smem offset for (row, 16-B granule c in 0..3), 64-B logical rows
__device__ __forceinline__ unsigned phys(int row, int c) {
    return ((unsigned)(row >> 1) << 7) + ((unsigned)(row & 1) << 6) +
           (((unsigned)(c ^ ((row >> 1) & 3))) << 4);
}

// ---------------------------------------------------------------------------
// Main: per chunk: cp.async -> HMMA (3-term fp16 split) -> RNE -> int acc
// CTA tile 128m x 64n, 8 warps 4(m) x 2(n), warp tile 32m x 32n.
// grid (16,16), 2 CTA/SM, double-buffered smem.
// ---------------------------------------------------------------------------
__global__ void __launch_bounds__(256, 2)
opu_main_kernel(float* __restrict__ out) {
    __shared__ __align__(1024) char sA[2][8192];   // 128 rows x 64 B (swizzled)
    __shared__ __align__(1024) char sB[2][4096];   // 64 rows x 64 B (swizzled)

    const int t = threadIdx.x, wid = t >> 5, lane = t & 31;
    const int m0 = blockIdx.x * 128, n0 = blockIdx.y * 64;
    const int wm = (wid >> 1) * 32, wn = (wid & 1) * 32;

    const unsigned sa = (unsigned)__cvta_generic_to_shared(&sA[0][0]);
    const unsigned sb = (unsigned)__cvta_generic_to_shared(&sB[0][0]);

    // staging: A 512 granules (2/thread), B 256 granules (1/thread)
    const int ar0 = t >> 2, ac0 = t & 3;           // granule t
    const int ar1 = (t + 256) >> 2, ac1 = t & 3;   // granule t+256
    const unsigned adst0 = phys(ar0, ac0), adst1 = phys(ar1, ac1);
    const unsigned bdst = phys(ar0, ac0);          // B uses same (row,c) map, rows<64

#define STAGE_CHUNK(r, buf)                                                    \
    do {                                                                       \
        const void* s0 = g_A + ((size_t)(r) * M_DIM + m0 + ar0) * 32 + ac0 * 8;\
        const void* s1 = g_A + ((size_t)(r) * M_DIM + m0 + ar1) * 32 + ac1 * 8;\
        const void* s2 = g_B + ((size_t)(r) * N_DIM + n0 + ar0) * 32 + ac0 * 8;\
        asm volatile("cp.async.cg.shared.global [%0], [%1], 16;" ::            \
                     "r"(sa + (buf) * 8192u + adst0), "l"(s0));                \
        asm volatile("cp.async.cg.shared.global [%0], [%1], 16;" ::            \
                     "r"(sa + (buf) * 8192u + adst1), "l"(s1));                \
        asm volatile("cp.async.cg.shared.global [%0], [%1], 16;" ::            \
                     "r"(sb + (buf) * 4096u + bdst), "l"(s2));                 \
    } while (0)

    // ldmatrix addresses
    const int l15 = lane & 15, lhi = lane >> 4;    // A: 16 rows, k8-half select
    const int l7 = lane & 7, lq = lane >> 3;       // B: 8 rows, granule select
    unsigned ahi_ad[2], alo_ad[2], b_ad[4];
#pragma unroll
    for (int i = 0; i < 2; i++) {
        int row = wm + 16 * i + l15;
        ahi_ad[i] = phys(row, lhi);        // hi: granules 0..1
        alo_ad[i] = phys(row, 2 + lhi);    // lo: granules 2..3
    }
#pragma unroll
    for (int j = 0; j < 4; j++) {
        int row = wn + 8 * j + l7;
        b_ad[j] = phys(row, lq);           // whi: mats 0-1, wlo: mats 2-3
    }

    unsigned su[2][4][4];
#pragma unroll
    for (int i = 0; i < 2; i++)
#pragma unroll
        for (int j = 0; j < 4; j++)
#pragma unroll
            for (int e = 0; e < 4; e++) su[i][j][e] = 0u;

    STAGE_CHUNK(0, 0);
    asm volatile("cp.async.commit_group;");
    STAGE_CHUNK(1, 1);
    asm volatile("cp.async.commit_group;");

    for (int r = 0; r < NCHUNK; r++) {
        const int b = r & 1;
        asm volatile("cp.async.wait_group 1;" ::: "memory");
        __syncthreads();

        unsigned bfr[4][4], ah[2][4], al[2][4];
#pragma unroll
        for (int j = 0; j < 4; j++) LDSM4(bfr[j], sb + b * 4096u + b_ad[j]);
#pragma unroll
        for (int i = 0; i < 2; i++) LDSM4(ah[i], sa + b * 8192u + ahi_ad[i]);
#pragma unroll
        for (int i = 0; i < 2; i++) LDSM4(al[i], sa + b * 8192u + alo_ad[i]);

        float acc[2][4][4];
#pragma unroll
        for (int i = 0; i < 2; i++)
#pragma unroll
            for (int j = 0; j < 4; j++)
#pragma unroll
                for (int e = 0; e < 4; e++) acc[i][j][e] = 0.0f;

#pragma unroll
        for (int i = 0; i < 2; i++)
#pragma unroll
            for (int j = 0; j < 4; j++) {
                MMA16816(acc[i][j], ah[i][0], ah[i][1], ah[i][2], ah[i][3],
                         bfr[j][0], bfr[j][1]);                  // hi*whi
                MMA16816(acc[i][j], ah[i][0], ah[i][1], ah[i][2], ah[i][3],
                         bfr[j][2], bfr[j][3]);                  // hi*wlo
                MMA16816(acc[i][j], al[i][0], al[i][1], al[i][2], al[i][3],
                         bfr[j][0], bfr[j][1]);                  // lo*whi
            }

        // ADC: acc = mm/16; +magic (1.5*2^23) -> RNE int in mantissa; int acc.
        // Clip never fires (|mm/16| <= 67 < 127.5).
#pragma unroll
        for (int i = 0; i < 2; i++)
#pragma unroll
            for (int j = 0; j < 4; j++)
#pragma unroll
                for (int e = 0; e < 4; e++) {
                    float tt = acc[i][j][e] + 12582912.0f;
                    su[i][j][e] += __float_as_uint(tt);
                }

        __syncthreads();
        if (r + 2 < NCHUNK) STAGE_CHUNK(r + 2, b);
        asm volatile("cp.async.commit_group;");
    }

    // out = 16 * (su - 64*0x4B400000 mod 2^32)
    const unsigned BIAS64 = 0xD0000000u;
    const int g = lane >> 2, tg = lane & 3;
#pragma unroll
    for (int i = 0; i < 2; i++)
#pragma unroll
        for (int h = 0; h < 2; h++) {
            int row = m0 + wm + 16 * i + 8 * h + g;
            float* orow = out + (size_t)row * N_DIM + n0 + wn + 2 * tg;
#pragma unroll
            for (int j = 0; j < 4; j++) {
                float2 o;
                o.x = 16.0f * (float)(int)(su[i][j][2 * h + 0] - BIAS64);
                o.y = 16.0f * (float)(int)(su[i][j][2 * h + 1] - BIAS64);
                *(float2*)(orow + 8 * j) = o;
            }
        }
#undef STAGE_CHUNK
}

// ---------------------------------------------------------------------------
extern "C" void kernel_launch(void* const* d_in, const int* in_sizes, int n_in,
                              void* d_out, int out_size) {
    const float* X    = (const float*)d_in[0];  // (2,1024,1024)
    const float* W    = (const float*)d_in[1];  // (1024,1024)
    const float* vmap = (const float*)d_in[2];  // (16,16)
    const float* wmap = (const float*)d_in[3];  // (16,16)
    float* out = (float*)d_out;                 // (2,1024,1024)

    prep_kernel<<<768, 256>>>(X, W, vmap, wmap);
    opu_main_kernel<<<dim3(16, 16), 256>>>(out);
}

// round 6
// speedup vs baseline: 1.5510x; 1.5510x over previous
#include <cuda_runtime.h>
#include <cuda_fp16.h>
#include <cstdint>

#define K_DIM 1024
#define M_DIM 2048
#define N_DIM 1024
#define NCHUNK 64
#define NPAIR  32

// fp16 split planes, 64 B per row: A=[hi(32B)|lo(32B)], B=[whi(32B)|wlo(32B)]
__device__ __half g_A[(size_t)NCHUNK * M_DIM * 32];
__device__ __half g_B[(size_t)NCHUNK * N_DIM * 32];

// ---------------------------------------------------------------------------
// Fused prep: blocks [0,512) do X, [512,768) do W. LUTs staged in smem.
// ---------------------------------------------------------------------------
__global__ void prep_kernel(const float* __restrict__ X,
                            const float* __restrict__ W,
                            const float* __restrict__ vmap,
                            const float* __restrict__ wmap) {
    __shared__ float s_lut[256];
    const bool isX = blockIdx.x < 512;
    s_lut[threadIdx.x] = isX ? vmap[threadIdx.x] : wmap[threadIdx.x];
    __syncthreads();

    if (isX) {
        // ---- X: x_c/16 -> hi/lo. one thread per (r,m)
        int gid = blockIdx.x * 256 + threadIdx.x;
        int r = gid >> 11, m = gid & 2047;
        const float* src = X + (size_t)m * K_DIM + r * 16;
        float xs[16];
        ((float4*)xs)[0] = ((const float4*)src)[0];
        ((float4*)xs)[1] = ((const float4*)src)[1];
        ((float4*)xs)[2] = ((const float4*)src)[2];
        ((float4*)xs)[3] = ((const float4*)src)[3];
        unsigned hi[8], lo[8];
#pragma unroll
        for (int jj = 0; jj < 8; jj++) {
            unsigned short h[2], l[2];
#pragma unroll
            for (int e = 0; e < 2; e++) {
                int j = 2 * jj + e;
                float xv = xs[j];
                int idx = (int)(xv + 8.0f);
                idx = idx < 0 ? 0 : (idx > 15 ? 15 : idx);
                float xc = (xv + s_lut[j * 16 + idx]) * 0.0625f;
                __half hh = __float2half_rn(xc);
                __half ll = __float2half_rn(xc - __half2float(hh));
                h[e] = __half_as_ushort(hh);
                l[e] = __half_as_ushort(ll);
            }
            hi[jj] = h[0] | ((unsigned)h[1] << 16);
            lo[jj] = l[0] | ((unsigned)l[1] << 16);
        }
        uint4* dst = (uint4*)(g_A + ((size_t)r * M_DIM + m) * 32);
        dst[0] = make_uint4(hi[0], hi[1], hi[2], hi[3]);
        dst[1] = make_uint4(hi[4], hi[5], hi[6], hi[7]);
        dst[2] = make_uint4(lo[0], lo[1], lo[2], lo[3]);
        dst[3] = make_uint4(lo[4], lo[5], lo[6], lo[7]);
    } else {
        // ---- W: w_c -> hi/lo
        int idx4 = blockIdx.x - 512;            // 0..255
        int r = idx4 >> 2;
        int n = (idx4 & 3) * 256 + threadIdx.x;
        unsigned hi[8], lo[8];
#pragma unroll
        for (int jj = 0; jj < 8; jj++) {
            unsigned short h[2], l[2];
#pragma unroll
            for (int e = 0; e < 2; e++) {
                int j = 2 * jj + e;
                float w = W[(size_t)(16 * r + j) * N_DIM + n];
                int idx = (int)(w + 8.0f);
                idx = idx < 0 ? 0 : (idx > 15 ? 15 : idx);
                float wc = w + s_lut[j * 16 + idx];
                __half hh = __float2half_rn(wc);
                __half ll = __float2half_rn(wc - __half2float(hh));
                h[e] = __half_as_ushort(hh);
                l[e] = __half_as_ushort(ll);
            }
            hi[jj] = h[0] | ((unsigned)h[1] << 16);
            lo[jj] = l[0] | ((unsigned)l[1] << 16);
        }
        uint4* dst = (uint4*)(g_B + ((size_t)r * N_DIM + n) * 32);
        dst[0] = make_uint4(hi[0], hi[1], hi[2], hi[3]);
        dst[1] = make_uint4(hi[4], hi[5], hi[6], hi[7]);
        dst[2] = make_uint4(lo[0], lo[1], lo[2], lo[3]);
        dst[3] = make_uint4(lo[4], lo[5], lo[6], lo[7]);
    }
}

// ---------------------------------------------------------------------------
#define LDSM4(R, addr)                                                         \
    asm volatile("ldmatrix.sync.aligned.m8n8.x4.shared.b16 {%0,%1,%2,%3}, [%4];" \
                 : "=r"((R)[0]), "=r"((R)[1]), "=r"((R)[2]), "=r"((R)[3])      \
                 : "r"(addr))

#define MMA16816(C, A0, A1, A2, A3, B0, B1)                                    \
    asm volatile("mma.sync.aligned.m16n8k16.row.col.f32.f16.f16.f32 "          \
                 "{%0,%1,%2,%3}, {%4,%5,%6,%7}, {%8,%9}, {%0,%1,%2,%3};"       \
                 : "+f"((C)[0]), "+f"((C)[1]), "+f"((C)[2]), "+f"((C)[3])      \
                 : "r"(A0), "r"(A1), "r"(A2), "r"(A3), "r"(B0), "r"(B1))

// swizzled smem offset for (row, 16-B granule c in 0..3), 64-B logical rows
__device__ __forceinline__ unsigned phys(int row, int c) {
    return ((unsigned)(row >> 1) << 7) + ((unsigned)(row & 1) << 6) +
           (((unsigned)(c ^ ((row >> 1) & 3))) << 4);
}

// pair-stage layout: A(even) 8K | A(odd) 8K | B(even) 4K | B(odd) 4K = 24 KB
#define STG_BYTES 24576u
#define A_OFF(c)  (((unsigned)(c) & 1u) * 8192u)
#define B_OFF(c)  (16384u + ((unsigned)(c) & 1u) * 4096u)

// ---------------------------------------------------------------------------
// Main: pair-processed chunks, 3-stage pipeline, ONE syncthreads per pair.
// CTA tile 128m x 64n, 8 warps 4(m) x 2(n), warp tile 32m x 32n.
// grid (16,16), 2 CTA/SM, 72 KB dynamic smem.
// ---------------------------------------------------------------------------
__global__ void __launch_bounds__(256, 2)
opu_main_kernel(float* __restrict__ out) {
    extern __shared__ __align__(1024) char smem[];
    const unsigned sb0 = (unsigned)__cvta_generic_to_shared(smem);

    const int t = threadIdx.x, wid = t >> 5, lane = t & 31;
    const int m0 = blockIdx.x * 128, n0 = blockIdx.y * 64;
    const int wm = (wid >> 1) * 32, wn = (wid & 1) * 32;

    // staging: per chunk, A 512 granules (2/thread), B 256 granules (1/thread)
    const int ar0 = t >> 2, ac0 = t & 3;
    const int ar1 = (t + 256) >> 2;
    const unsigned adst0 = phys(ar0, ac0), adst1 = phys(ar1, ac0);
    const unsigned bdst = phys(ar0, ac0);

#define STAGE_PAIR(p, s)                                                        \
    do {                                                                        \
        unsigned base = sb0 + (s) * STG_BYTES;                                  \
        _Pragma("unroll")                                                       \
        for (int c = 0; c < 2; c++) {                                           \
            int ch = 2 * (p) + c;                                               \
            const void* s0 = g_A + ((size_t)ch * M_DIM + m0 + ar0) * 32 + ac0 * 8; \
            const void* s1 = g_A + ((size_t)ch * M_DIM + m0 + ar1) * 32 + ac0 * 8; \
            const void* s2 = g_B + ((size_t)ch * N_DIM + n0 + ar0) * 32 + ac0 * 8; \
            asm volatile("cp.async.cg.shared.global [%0], [%1], 16;" ::        \
                         "r"(base + A_OFF(c) + adst0), "l"(s0));               \
            asm volatile("cp.async.cg.shared.global [%0], [%1], 16;" ::        \
                         "r"(base + A_OFF(c) + adst1), "l"(s1));               \
            asm volatile("cp.async.cg.shared.global [%0], [%1], 16;" ::        \
                         "r"(base + B_OFF(c) + bdst), "l"(s2));                \
        }                                                                       \
    } while (0)

    // ldmatrix addresses
    const int l15 = lane & 15, lhi = lane >> 4;
    const int l7 = lane & 7, lq = lane >> 3;
    unsigned ahi_ad[2], alo_ad[2], b_ad[4];
#pragma unroll
    for (int i = 0; i < 2; i++) {
        int row = wm + 16 * i + l15;
        ahi_ad[i] = phys(row, lhi);
        alo_ad[i] = phys(row, 2 + lhi);
    }
#pragma unroll
    for (int j = 0; j < 4; j++) {
        int row = wn + 8 * j + l7;
        b_ad[j] = phys(row, lq);
    }

    unsigned su[2][4][4];
#pragma unroll
    for (int i = 0; i < 2; i++)
#pragma unroll
        for (int j = 0; j < 4; j++)
#pragma unroll
            for (int e = 0; e < 4; e++) su[i][j][e] = 0u;

    STAGE_PAIR(0, 0);
    asm volatile("cp.async.commit_group;");
    STAGE_PAIR(1, 1);
    asm volatile("cp.async.commit_group;");

    int cur = 0;
    for (int p = 0; p < NPAIR; p++) {
        asm volatile("cp.async.wait_group 1;" ::: "memory");
        __syncthreads();

        int nxt = cur + 2; if (nxt >= 3) nxt -= 3;
        if (p + 2 < NPAIR) STAGE_PAIR(p + 2, nxt);
        asm volatile("cp.async.commit_group;");

        const unsigned base = sb0 + cur * STG_BYTES;

#pragma unroll
        for (int c = 0; c < 2; c++) {
            const unsigned ab = base + A_OFF(c);
            const unsigned bb = base + B_OFF(c);

            unsigned bfr[4][4], ah[2][4], al[2][4];
#pragma unroll
            for (int j = 0; j < 4; j++) LDSM4(bfr[j], bb + b_ad[j]);
#pragma unroll
            for (int i = 0; i < 2; i++) LDSM4(ah[i], ab + ahi_ad[i]);
#pragma unroll
            for (int i = 0; i < 2; i++) LDSM4(al[i], ab + alo_ad[i]);

            float acc[2][4][4];
#pragma unroll
            for (int i = 0; i < 2; i++)
#pragma unroll
                for (int j = 0; j < 4; j++)
#pragma unroll
                    for (int e = 0; e < 4; e++) acc[i][j][e] = 0.0f;

#pragma unroll
            for (int i = 0; i < 2; i++)
#pragma unroll
                for (int j = 0; j < 4; j++) {
                    MMA16816(acc[i][j], ah[i][0], ah[i][1], ah[i][2], ah[i][3],
                             bfr[j][0], bfr[j][1]);                  // hi*whi
                    MMA16816(acc[i][j], ah[i][0], ah[i][1], ah[i][2], ah[i][3],
                             bfr[j][2], bfr[j][3]);                  // hi*wlo
                    MMA16816(acc[i][j], al[i][0], al[i][1], al[i][2], al[i][3],
                             bfr[j][0], bfr[j][1]);                  // lo*whi
                }

            // ADC: acc = mm/16; +magic (1.5*2^23) -> RNE int in mantissa.
            // Clip never fires (|mm/16| <= 67 < 127.5).
#pragma unroll
            for (int i = 0; i < 2; i++)
#pragma unroll
                for (int j = 0; j < 4; j++)
#pragma unroll
                    for (int e = 0; e < 4; e++) {
                        float tt = acc[i][j][e] + 12582912.0f;
                        su[i][j][e] += __float_as_uint(tt);
                    }
        }

        cur = cur + 1; if (cur >= 3) cur -= 3;
    }

    // out = 16 * (su - 64*0x4B400000 mod 2^32)
    const unsigned BIAS64 = 0xD0000000u;
    const int g = lane >> 2, tg = lane & 3;
#pragma unroll
    for (int i = 0; i < 2; i++)
#pragma unroll
        for (int h = 0; h < 2; h++) {
            int row = m0 + wm + 16 * i + 8 * h + g;
            float* orow = out + (size_t)row * N_DIM + n0 + wn + 2 * tg;
#pragma unroll
            for (int j = 0; j < 4; j++) {
                float2 o;
                o.x = 16.0f * (float)(int)(su[i][j][2 * h + 0] - BIAS64);
                o.y = 16.0f * (float)(int)(su[i][j][2 * h + 1] - BIAS64);
                *(float2*)(orow + 8 * j) = o;
            }
        }
#undef STAGE_PAIR
}

// ---------------------------------------------------------------------------
extern "C" void kernel_launch(void* const* d_in, const int* in_sizes, int n_in,
                              void* d_out, int out_size) {
    const float* X    = (const float*)d_in[0];  // (2,1024,1024)
    const float* W    = (const float*)d_in[1];  // (1024,1024)
    const float* vmap = (const float*)d_in[2];  // (16,16)
    const float* wmap = (const float*)d_in[3];  // (16,16)
    float* out = (float*)d_out;                 // (2,1024,1024)

    cudaFuncSetAttribute(opu_main_kernel,
                         cudaFuncAttributeMaxDynamicSharedMemorySize, 3 * 24576);

    prep_kernel<<<768, 256>>>(X, W, vmap, wmap);
    opu_main_kernel<<<dim3(16, 16), 256, 3 * 24576>>>(out);
}